// round 8
// baseline (speedup 1.0000x reference)
#include <cuda_runtime.h>
#include <cstdint>

#define FILLV (-1000.0f)
#define NEG_BIG (-3.0e38f)

// Per-batch scratch (allocation-free rule: __device__ globals).
__device__ float g_total[512];
__device__ float g_real[512];

// ---- f32x2 / b64 helpers -------------------------------------------------
__device__ __forceinline__ unsigned long long pk2(float x, float y) {
    unsigned long long r;
    asm("mov.b64 %0, {%1, %2};" : "=l"(r) : "f"(x), "f"(y));
    return r;
}
__device__ __forceinline__ void upk2(unsigned long long a, float& x, float& y) {
    asm("mov.b64 {%0, %1}, %2;" : "=f"(x), "=f"(y) : "l"(a));
}
__device__ __forceinline__ unsigned long long fma2(unsigned long long a,
                                                   unsigned long long b,
                                                   unsigned long long c) {
    unsigned long long r;
    asm("fma.rn.f32x2 %0, %1, %2, %3;" : "=l"(r) : "l"(a), "l"(b), "l"(c));
    return r;
}
__device__ __forceinline__ unsigned long long add2(unsigned long long a,
                                                   unsigned long long b) {
    unsigned long long r;
    asm("add.rn.f32x2 %0, %1, %2;" : "=l"(r) : "l"(a), "l"(b));
    return r;
}

// Dynamic shared memory layout (bytes):
//   shpv : 2 * 64 * 16  = 2048   (per batch: {pre[2m],pre[2m+1] | v[2m],v[2m+1]})
//   sEp  : 64 * 128 * 8 = 65536  (float2 per row-pair per column; batch-indep)
//   spc  : 2 * 256 * 4  = 2048
//   spw  : 2 * 256 * 4  = 2048
//   scol : 128 * 4      = 512
//   swS  : 2 * 4 * 4    = 32
//   swM  : 2 * 4 * 4    = 32
#define SM_SHPV 0
#define SM_EP   (SM_SHPV + 2048)
#define SM_SPC  (SM_EP + 65536)
#define SM_SPW  (SM_SPC + 2048)
#define SM_SCOL (SM_SPW + 2048)
#define SM_SWS  (SM_SCOL + 512)
#define SM_SWM  (SM_SWS + 32)
#define SM_TOTAL (SM_SWM + 32)

// ---- forward (total path score) kernel -----------------------------------
// 2 batches per CTA, grid = 256, block = 256, occ 2 (two independent CTAs
// per SM overlap each other's barriers/serial tails).
// Thread t: column jj = t & 127, row-half h = t >> 7 (rows h*64 .. h*64+63).
// Tc2[32] (64 regs) in registers; Ep in shared (read once per k, both batches).
// Phase 0: every thread processes both batches (ILP-2).
// Phases 1/2: half h owns batch h.
__global__ void __launch_bounds__(256, 2)
crf_forward_kernel(const float* __restrict__ em, const float* __restrict__ trans) {
    extern __shared__ char raw[];
    ulonglong2* shpv = (ulonglong2*)(raw + SM_SHPV);      // [2][64]
    float2*     sEp  = (float2*)(raw + SM_EP);            // [64][128]
    float*      spc  = (float*)(raw + SM_SPC);            // [2][256]
    float*      spw  = (float*)(raw + SM_SPW);            // [2][256]
    float*      scol = (float*)(raw + SM_SCOL);           // [128]
    float*      swS  = (float*)(raw + SM_SWS);            // [2][4]
    float*      swM  = (float*)(raw + SM_SWM);            // [2][4]

    const int t  = threadIdx.x;
    const int jj = t & 127;
    const int h  = t >> 7;               // half index; owns batch h
    const int b0 = blockIdx.x * 2;
    const int rowbase = h * 64;

    // --- load T column slice (64 rows), colmax, Tc2 regs + Ep smem ---
    float Tcs[64];
    float tcm = NEG_BIG;
#pragma unroll
    for (int k = 0; k < 64; ++k) {
        float tv = trans[(rowbase + k) * 128 + jj];
        Tcs[k] = tv;
        tcm = fmaxf(tcm, tv);
    }
    spc[t] = tcm;
    __syncthreads();
    if (t < 128) scol[t] = fmaxf(spc[t], spc[t + 128]);
    __syncthreads();
    const float colmax = scol[jj];

    unsigned long long Tc2[32];
#pragma unroll
    for (int k = 0; k < 32; ++k) {
        Tc2[k] = pk2(Tcs[2 * k], Tcs[2 * k + 1]);
        float2 e;
        e.x = expf(Tcs[2 * k] - colmax);
        e.y = expf(Tcs[2 * k + 1] - colmax);
        sEp[(h * 32 + k) * 128 + jj] = e;
    }

    // --- init state: half h initializes batch h ---
    {
        float p  = (jj == 126) ? 0.0f : FILLV;
        float vv = (jj == 126) ? 1.0f : 0.0f;
        int m = jj >> 1, lane = jj & 1;
        float* pvf = (float*)(shpv + h * 64);
        pvf[m * 4 + lane]     = p;
        pvf[m * 4 + 2 + lane] = vv;
    }
    float pmax = 0.0f;
    float Lacc = 0.0f;
    float vkeep = 0.0f;
    __syncthreads();

    const float* embp = em + (size_t)(b0 + h) * 512 * 126;

    // obs for step s=1 (emissions row 0), owned batch only
    float obs_c = (jj < 126) ? embp[jj] : FILLV;

    const ulonglong2* const pvA = shpv + h * 32;          // batch 0 rows
    const ulonglong2* const pvB = shpv + 64 + h * 32;     // batch 1 rows
    const float2* const epb = sEp + (size_t)(h * 32) * 128 + jj;

    for (int s = 1; s <= 513; ++s) {
        // Prefetch next step's observation (hidden behind phase 0).
        float obs_n;
        if (s + 1 <= 512) {
            obs_n = (jj < 126) ? embp[(size_t)s * 126 + jj] : FILLV;
        } else {
            obs_n = (jj == 127) ? 0.0f : FILLV;   // END pseudo-row
        }

        // --- phase 0: max-plus + matvec over this thread's 64 rows, 2 batches ---
        float cm0A = NEG_BIG, cm1A = NEG_BIG;
        float cm0B = NEG_BIG, cm1B = NEG_BIG;
        unsigned long long wA = 0ULL, wB = 0ULL;
#pragma unroll
        for (int k = 0; k < 32; ++k) {
            float2 e = epb[(size_t)k * 128];              // LDS.64, batch-indep
            unsigned long long ep = pk2(e.x, e.y);
            ulonglong2 qA = pvA[k];                       // LDS.128 broadcast
            ulonglong2 qB = pvB[k];
            float s0, s1;
            unsigned long long u;
            u = add2(qA.x, Tc2[k]); upk2(u, s0, s1);
            cm0A = fmaxf(cm0A, s0); cm1A = fmaxf(cm1A, s1);
            wA = fma2(qA.y, ep, wA);
            u = add2(qB.x, Tc2[k]); upk2(u, s0, s1);
            cm0B = fmaxf(cm0B, s0); cm1B = fmaxf(cm1B, s1);
            wB = fma2(qB.y, ep, wB);
        }
        {
            float w0, w1;
            upk2(wA, w0, w1); spc[t]       = fmaxf(cm0A, cm1A); spw[t]       = w0 + w1;
            upk2(wB, w0, w1); spc[256 + t] = fmaxf(cm0B, cm1B); spw[256 + t] = w0 + w1;
        }
        __syncthreads();

        // --- phase 1: half h combines + reduces its owned batch h ---
        float pnew;
        {
            const float* pc = spc + h * 256;
            const float* pw = spw + h * 256;
            float c = fmaxf(pc[jj], pc[jj + 128]);
            float w = pw[jj] + pw[jj + 128];
            float contrib = expf(pmax + colmax - c) * w;
            pnew = obs_c + c;

            float sred = contrib, mred = pnew;
#pragma unroll
            for (int o = 16; o; o >>= 1) {
                sred += __shfl_xor_sync(0xffffffffu, sred, o);
                mred = fmaxf(mred, __shfl_xor_sync(0xffffffffu, mred, o));
            }
            if ((t & 31) == 0) {
                const int wi = (t >> 5) & 3;
                swS[h * 4 + wi] = sred; swM[h * 4 + wi] = mred;
            }
        }
        // half-scoped barrier (ids 1,2): half h only reads swS/swM[h]
        asm volatile("bar.sync %0, 128;" :: "r"(h + 1) : "memory");

        // --- phase 2: scalar combine + publish new state for owned batch ---
        {
            float S  = (swS[h * 4 + 0] + swS[h * 4 + 1]) + (swS[h * 4 + 2] + swS[h * 4 + 3]);
            float pm = fmaxf(fmaxf(swM[h * 4 + 0], swM[h * 4 + 1]),
                             fmaxf(swM[h * 4 + 2], swM[h * 4 + 3]));
            Lacc += logf(S);
            float vv = expf(pnew - pm);
            vkeep = vv;
            int m = jj >> 1, lane = jj & 1;
            float* pvf = (float*)(shpv + h * 64);
            pvf[m * 4 + lane]     = pnew;
            pvf[m * 4 + 2 + lane] = vv;
            pmax = pm;
        }
        __syncthreads();
        obs_c = obs_n;
    }

    // --- final log-sum-exp for owned batch ---
    {
        float sred = vkeep;
#pragma unroll
        for (int o = 16; o; o >>= 1) sred += __shfl_xor_sync(0xffffffffu, sred, o);
        if ((t & 31) == 0) swS[h * 4 + ((t >> 5) & 3)] = sred;
    }
    asm volatile("bar.sync %0, 128;" :: "r"(h + 1) : "memory");
    if (jj == 0) {
        float Sf = (swS[h * 4 + 0] + swS[h * 4 + 1]) + (swS[h * 4 + 2] + swS[h * 4 + 3]);
        g_total[b0 + h] = pmax + logf(Sf) + Lacc;
    }
}

// ---- gold-path score kernel ----------------------------------------------
__global__ void crf_real_kernel(const float* __restrict__ em,
                                const int* __restrict__ labels,
                                const float* __restrict__ trans) {
    const int b = blockIdx.x;
    const int t = threadIdx.x;   // 128 threads
    __shared__ float sw[4];
    const int* lb = labels + b * 512;
    const float* emb = em + (size_t)b * 512 * 126;

    float acc = 0.0f;
    for (int tt = t; tt < 512; tt += 128) {
        int l0 = lb[tt];
        acc += emb[tt * 126 + l0];
        int l1 = (tt < 511) ? lb[tt + 1] : 127;     // END = L+1 = 127
        acc += trans[l0 * 128 + l1];
    }
    if (t == 0) acc += trans[126 * 128 + lb[0]];     // START = L = 126

#pragma unroll
    for (int o = 16; o; o >>= 1) acc += __shfl_xor_sync(0xffffffffu, acc, o);
    if ((t & 31) == 0) sw[t >> 5] = acc;
    __syncthreads();
    if (t == 0) g_real[b] = (sw[0] + sw[1]) + (sw[2] + sw[3]);
}

// ---- fixed-order final reduction (deterministic) -------------------------
__global__ void crf_reduce_kernel(float* __restrict__ out) {
    const int t = threadIdx.x;   // 512 threads
    __shared__ float sw[16];
    float d = g_total[t] - g_real[t];
#pragma unroll
    for (int o = 16; o; o >>= 1) d += __shfl_xor_sync(0xffffffffu, d, o);
    if ((t & 31) == 0) sw[t >> 5] = d;
    __syncthreads();
    if (t == 0) {
        float s = 0.0f;
#pragma unroll
        for (int w = 0; w < 16; ++w) s += sw[w];
        out[0] = s;
    }
}

extern "C" void kernel_launch(void* const* d_in, const int* in_sizes, int n_in,
                              void* d_out, int out_size) {
    const float* em     = (const float*)d_in[0];   // [512, 512, 126] f32
    const int*   labels = (const int*)d_in[1];     // [512, 512] i32
    const float* trans  = (const float*)d_in[2];   // [128, 128] f32

    static int configured = 0;
    if (!configured) {
        cudaFuncSetAttribute(crf_forward_kernel,
                             cudaFuncAttributeMaxDynamicSharedMemorySize, SM_TOTAL);
        configured = 1;
    }

    crf_forward_kernel<<<256, 256, SM_TOTAL>>>(em, trans);
    crf_real_kernel<<<512, 128>>>(em, labels, trans);
    crf_reduce_kernel<<<1, 512>>>((float*)d_out);
}

// round 10
// speedup vs baseline: 1.0707x; 1.0707x over previous
#include <cuda_runtime.h>
#include <cstdint>

#define FILLV (-1000.0f)
#define NEG_BIG (-3.0e38f)

// Per-batch scratch (allocation-free rule: __device__ globals).
__device__ float g_total[512];
__device__ float g_real[512];

// ---- f32x2 / b64 helpers -------------------------------------------------
__device__ __forceinline__ unsigned long long pk2(float x, float y) {
    unsigned long long r;
    asm("mov.b64 %0, {%1, %2};" : "=l"(r) : "f"(x), "f"(y));
    return r;
}
__device__ __forceinline__ void upk2(unsigned long long a, float& x, float& y) {
    asm("mov.b64 {%0, %1}, %2;" : "=f"(x), "=f"(y) : "l"(a));
}
__device__ __forceinline__ unsigned long long fma2(unsigned long long a,
                                                   unsigned long long b,
                                                   unsigned long long c) {
    unsigned long long r;
    asm("fma.rn.f32x2 %0, %1, %2, %3;" : "=l"(r) : "l"(a), "l"(b), "l"(c));
    return r;
}
__device__ __forceinline__ unsigned long long add2(unsigned long long a,
                                                   unsigned long long b) {
    unsigned long long r;
    asm("add.rn.f32x2 %0, %1, %2;" : "=l"(r) : "l"(a), "l"(b));
    return r;
}

// Dynamic shared memory layout (bytes):
//   sEp  : 64 * 128 * 8 = 65536  (float2 Ep per row-pair per column; batch-indep)
//   shpv : 4 * 64 * 16  = 4096   (per batch: {pre[2m],pre[2m+1] | v[2m],v[2m+1]})
//   spc  : 4 * 256 * 4  = 4096
//   spw  : 4 * 256 * 4  = 4096
//   scol : 128 * 4      = 512
//   swS  : 4 * 4 * 4    = 64
//   swM  : 4 * 4 * 4    = 64
#define SM_EP   0
#define SM_SHPV (SM_EP + 65536)
#define SM_SPC  (SM_SHPV + 4096)
#define SM_SPW  (SM_SPC + 4096)
#define SM_SCOL (SM_SPW + 4096)
#define SM_SWS  (SM_SCOL + 512)
#define SM_SWM  (SM_SWS + 64)
#define SM_TOTAL (SM_SWM + 64)

// ---- forward (total path score) kernel -----------------------------------
// 4 batches per CTA. grid = 128 (1 wave), block = 256.
// Thread t: column jj = t & 127, row-half h = t >> 7 (rows h*64 .. h*64+63).
// Tc2[32] (64 regs) in registers; Ep in shared (1 LDS.64/iter, amortized 4x).
// Phase 0: all threads, all 4 batches (ILP-4), pv loads pipelined 1 ahead.
// Phases 1/2: half h owns batches 2h, 2h+1; interleaved shfl reductions.
__global__ void __launch_bounds__(256, 1)
crf_forward_kernel(const float* __restrict__ em, const float* __restrict__ trans) {
    extern __shared__ char raw[];
    float2*     sEp  = (float2*)(raw + SM_EP);            // [64][128]
    ulonglong2* shpv = (ulonglong2*)(raw + SM_SHPV);      // [4][64]
    float*      spc  = (float*)(raw + SM_SPC);            // [4][256]
    float*      spw  = (float*)(raw + SM_SPW);            // [4][256]
    float*      scol = (float*)(raw + SM_SCOL);           // [128]
    float*      swS  = (float*)(raw + SM_SWS);            // [4][4]
    float*      swM  = (float*)(raw + SM_SWM);            // [4][4]

    const int t  = threadIdx.x;
    const int jj = t & 127;
    const int h  = t >> 7;
    const int b0 = blockIdx.x * 4;
    const int rowbase = h * 64;

    // --- load T column slice, colmax, Tc2 regs + Ep smem ---
    float Tcs[64];
    float tcm = NEG_BIG;
#pragma unroll
    for (int k = 0; k < 64; ++k) {
        float tv = trans[(rowbase + k) * 128 + jj];
        Tcs[k] = tv;
        tcm = fmaxf(tcm, tv);
    }
    spc[t] = tcm;
    __syncthreads();
    if (t < 128) scol[t] = fmaxf(spc[t], spc[t + 128]);
    __syncthreads();
    const float colmax = scol[jj];

    unsigned long long Tc2[32];
#pragma unroll
    for (int k = 0; k < 32; ++k) {
        Tc2[k] = pk2(Tcs[2 * k], Tcs[2 * k + 1]);
        float2 e;
        e.x = expf(Tcs[2 * k] - colmax);
        e.y = expf(Tcs[2 * k + 1] - colmax);
        sEp[(h * 32 + k) * 128 + jj] = e;
    }

    // --- init state for owned batches g0 = 2h, g1 = 2h+1 ---
    {
        float p  = (jj == 126) ? 0.0f : FILLV;
        float vv = (jj == 126) ? 1.0f : 0.0f;
        int m = jj >> 1, lane = jj & 1;
        float* pvf0 = (float*)(shpv + (2 * h) * 64);
        float* pvf1 = (float*)(shpv + (2 * h + 1) * 64);
        pvf0[m * 4 + lane] = p;  pvf0[m * 4 + 2 + lane] = vv;
        pvf1[m * 4 + lane] = p;  pvf1[m * 4 + 2 + lane] = vv;
    }
    float pmax0 = 0.0f, pmax1 = 0.0f;
    float Lacc0 = 0.0f, Lacc1 = 0.0f;
    float vkeep0 = 0.0f, vkeep1 = 0.0f;
    __syncthreads();

    const float* embp0 = em + (size_t)(b0 + 2 * h) * 512 * 126;
    const float* embp1 = embp0 + 512 * 126;

    float obs_c0 = (jj < 126) ? embp0[jj] : FILLV;
    float obs_c1 = (jj < 126) ? embp1[jj] : FILLV;

    const ulonglong2* const pvA = shpv + 0 * 64 + h * 32;
    const ulonglong2* const pvB = shpv + 1 * 64 + h * 32;
    const ulonglong2* const pvC = shpv + 2 * 64 + h * 32;
    const ulonglong2* const pvD = shpv + 3 * 64 + h * 32;
    const float2* const epb = sEp + (size_t)(h * 32) * 128 + jj;

    for (int s = 1; s <= 513; ++s) {
        // Prefetch next step's observations (hidden behind phase 0).
        float obs_n0, obs_n1;
        if (s + 1 <= 512) {
            obs_n0 = (jj < 126) ? embp0[(size_t)s * 126 + jj] : FILLV;
            obs_n1 = (jj < 126) ? embp1[(size_t)s * 126 + jj] : FILLV;
        } else {
            float v = (jj == 127) ? 0.0f : FILLV;  // END pseudo-row
            obs_n0 = v; obs_n1 = v;
        }

        // --- phase 0: max-plus + matvec, 64 rows x 4 batches, pipelined ---
        float cm0A = NEG_BIG, cm1A = NEG_BIG;
        float cm0B = NEG_BIG, cm1B = NEG_BIG;
        float cm0C = NEG_BIG, cm1C = NEG_BIG;
        float cm0D = NEG_BIG, cm1D = NEG_BIG;
        unsigned long long wA = 0ULL, wB = 0ULL, wC = 0ULL, wD = 0ULL;

        ulonglong2 qA = pvA[0], qB = pvB[0], qC = pvC[0], qD = pvD[0];
        float2 ef = epb[0];
#pragma unroll
        for (int k = 0; k < 32; ++k) {
            // stage next iteration's loads before consuming current
            ulonglong2 nA, nB, nC, nD; float2 ne;
            if (k < 31) {
                nA = pvA[k + 1]; nB = pvB[k + 1];
                nC = pvC[k + 1]; nD = pvD[k + 1];
                ne = epb[(size_t)(k + 1) * 128];
            }
            unsigned long long ep = pk2(ef.x, ef.y);
            float s0, s1;
            unsigned long long u;
            u = add2(qA.x, Tc2[k]); upk2(u, s0, s1);
            cm0A = fmaxf(cm0A, s0); cm1A = fmaxf(cm1A, s1);
            wA = fma2(qA.y, ep, wA);
            u = add2(qB.x, Tc2[k]); upk2(u, s0, s1);
            cm0B = fmaxf(cm0B, s0); cm1B = fmaxf(cm1B, s1);
            wB = fma2(qB.y, ep, wB);
            u = add2(qC.x, Tc2[k]); upk2(u, s0, s1);
            cm0C = fmaxf(cm0C, s0); cm1C = fmaxf(cm1C, s1);
            wC = fma2(qC.y, ep, wC);
            u = add2(qD.x, Tc2[k]); upk2(u, s0, s1);
            cm0D = fmaxf(cm0D, s0); cm1D = fmaxf(cm1D, s1);
            wD = fma2(qD.y, ep, wD);
            if (k < 31) { qA = nA; qB = nB; qC = nC; qD = nD; ef = ne; }
        }
        {
            float w0, w1;
            upk2(wA, w0, w1); spc[0 * 256 + t] = fmaxf(cm0A, cm1A); spw[0 * 256 + t] = w0 + w1;
            upk2(wB, w0, w1); spc[1 * 256 + t] = fmaxf(cm0B, cm1B); spw[1 * 256 + t] = w0 + w1;
            upk2(wC, w0, w1); spc[2 * 256 + t] = fmaxf(cm0C, cm1C); spw[2 * 256 + t] = w0 + w1;
            upk2(wD, w0, w1); spc[3 * 256 + t] = fmaxf(cm0D, cm1D); spw[3 * 256 + t] = w0 + w1;
        }
        __syncthreads();

        // --- phase 1: half h combines + reduces its 2 owned batches ---
        const int g0 = 2 * h, g1 = g0 + 1;
        float pnew0, pnew1;
        {
            float c0 = fmaxf(spc[g0 * 256 + jj], spc[g0 * 256 + 128 + jj]);
            float w0 = spw[g0 * 256 + jj] + spw[g0 * 256 + 128 + jj];
            float contrib0 = __expf(pmax0 + colmax - c0) * w0;
            pnew0 = obs_c0 + c0;
            float c1 = fmaxf(spc[g1 * 256 + jj], spc[g1 * 256 + 128 + jj]);
            float w1 = spw[g1 * 256 + jj] + spw[g1 * 256 + 128 + jj];
            float contrib1 = __expf(pmax1 + colmax - c1) * w1;
            pnew1 = obs_c1 + c1;

            // interleaved butterfly: 4 chains overlap their SHFL latencies
            float sr0 = contrib0, mr0 = pnew0;
            float sr1 = contrib1, mr1 = pnew1;
#pragma unroll
            for (int o = 16; o; o >>= 1) {
                float a0 = __shfl_xor_sync(0xffffffffu, sr0, o);
                float b0m = __shfl_xor_sync(0xffffffffu, mr0, o);
                float a1 = __shfl_xor_sync(0xffffffffu, sr1, o);
                float b1m = __shfl_xor_sync(0xffffffffu, mr1, o);
                sr0 += a0; mr0 = fmaxf(mr0, b0m);
                sr1 += a1; mr1 = fmaxf(mr1, b1m);
            }
            if ((t & 31) == 0) {
                const int wi = (t >> 5) & 3;
                swS[g0 * 4 + wi] = sr0; swM[g0 * 4 + wi] = mr0;
                swS[g1 * 4 + wi] = sr1; swM[g1 * 4 + wi] = mr1;
            }
        }
        // half-scoped barrier (ids 1,2): half h only reads swS/swM[g0,g1]
        asm volatile("bar.sync %0, 128;" :: "r"(h + 1) : "memory");

        // --- phase 2: scalar combine + publish new state for owned batches ---
        {
            float S0 = (swS[g0 * 4 + 0] + swS[g0 * 4 + 1]) + (swS[g0 * 4 + 2] + swS[g0 * 4 + 3]);
            float S1 = (swS[g1 * 4 + 0] + swS[g1 * 4 + 1]) + (swS[g1 * 4 + 2] + swS[g1 * 4 + 3]);
            float pm0 = fmaxf(fmaxf(swM[g0 * 4 + 0], swM[g0 * 4 + 1]),
                              fmaxf(swM[g0 * 4 + 2], swM[g0 * 4 + 3]));
            float pm1 = fmaxf(fmaxf(swM[g1 * 4 + 0], swM[g1 * 4 + 1]),
                              fmaxf(swM[g1 * 4 + 2], swM[g1 * 4 + 3]));
            Lacc0 += __logf(S0);
            Lacc1 += __logf(S1);
            float vv0 = __expf(pnew0 - pm0);
            float vv1 = __expf(pnew1 - pm1);
            vkeep0 = vv0; vkeep1 = vv1;
            int m = jj >> 1, lane = jj & 1;
            float* pvf0 = (float*)(shpv + g0 * 64);
            float* pvf1 = (float*)(shpv + g1 * 64);
            pvf0[m * 4 + lane] = pnew0;  pvf0[m * 4 + 2 + lane] = vv0;
            pvf1[m * 4 + lane] = pnew1;  pvf1[m * 4 + 2 + lane] = vv1;
            pmax0 = pm0; pmax1 = pm1;
        }
        __syncthreads();
        obs_c0 = obs_n0;
        obs_c1 = obs_n1;
    }

    // --- final log-sum-exp per owned batch ---
    {
        float sr0 = vkeep0, sr1 = vkeep1;
#pragma unroll
        for (int o = 16; o; o >>= 1) {
            sr0 += __shfl_xor_sync(0xffffffffu, sr0, o);
            sr1 += __shfl_xor_sync(0xffffffffu, sr1, o);
        }
        if ((t & 31) == 0) {
            const int wi = (t >> 5) & 3;
            swS[(2 * h) * 4 + wi] = sr0;
            swS[(2 * h + 1) * 4 + wi] = sr1;
        }
    }
    asm volatile("bar.sync %0, 128;" :: "r"(h + 1) : "memory");
    if (jj == 0) {
        const int g0 = 2 * h, g1 = g0 + 1;
        float Sf0 = (swS[g0 * 4 + 0] + swS[g0 * 4 + 1]) + (swS[g0 * 4 + 2] + swS[g0 * 4 + 3]);
        float Sf1 = (swS[g1 * 4 + 0] + swS[g1 * 4 + 1]) + (swS[g1 * 4 + 2] + swS[g1 * 4 + 3]);
        g_total[b0 + g0] = pmax0 + logf(Sf0) + Lacc0;
        g_total[b0 + g1] = pmax1 + logf(Sf1) + Lacc1;
    }
}

// ---- gold-path score kernel ----------------------------------------------
__global__ void crf_real_kernel(const float* __restrict__ em,
                                const int* __restrict__ labels,
                                const float* __restrict__ trans) {
    const int b = blockIdx.x;
    const int t = threadIdx.x;   // 128 threads
    __shared__ float sw[4];
    const int* lb = labels + b * 512;
    const float* emb = em + (size_t)b * 512 * 126;

    float acc = 0.0f;
    for (int tt = t; tt < 512; tt += 128) {
        int l0 = lb[tt];
        acc += emb[tt * 126 + l0];
        int l1 = (tt < 511) ? lb[tt + 1] : 127;     // END = L+1 = 127
        acc += trans[l0 * 128 + l1];
    }
    if (t == 0) acc += trans[126 * 128 + lb[0]];     // START = L = 126

#pragma unroll
    for (int o = 16; o; o >>= 1) acc += __shfl_xor_sync(0xffffffffu, acc, o);
    if ((t & 31) == 0) sw[t >> 5] = acc;
    __syncthreads();
    if (t == 0) g_real[b] = (sw[0] + sw[1]) + (sw[2] + sw[3]);
}

// ---- fixed-order final reduction (deterministic) -------------------------
__global__ void crf_reduce_kernel(float* __restrict__ out) {
    const int t = threadIdx.x;   // 512 threads
    __shared__ float sw[16];
    float d = g_total[t] - g_real[t];
#pragma unroll
    for (int o = 16; o; o >>= 1) d += __shfl_xor_sync(0xffffffffu, d, o);
    if ((t & 31) == 0) sw[t >> 5] = d;
    __syncthreads();
    if (t == 0) {
        float s = 0.0f;
#pragma unroll
        for (int w = 0; w < 16; ++w) s += sw[w];
        out[0] = s;
    }
}

extern "C" void kernel_launch(void* const* d_in, const int* in_sizes, int n_in,
                              void* d_out, int out_size) {
    const float* em     = (const float*)d_in[0];   // [512, 512, 126] f32
    const int*   labels = (const int*)d_in[1];     // [512, 512] i32
    const float* trans  = (const float*)d_in[2];   // [128, 128] f32

    static int configured = 0;
    if (!configured) {
        cudaFuncSetAttribute(crf_forward_kernel,
                             cudaFuncAttributeMaxDynamicSharedMemorySize, SM_TOTAL);
        configured = 1;
    }

    crf_forward_kernel<<<128, 256, SM_TOTAL>>>(em, trans);
    crf_real_kernel<<<512, 128>>>(em, labels, trans);
    crf_reduce_kernel<<<1, 512>>>((float*)d_out);
}

// round 11
// speedup vs baseline: 1.4353x; 1.3405x over previous
#include <cuda_runtime.h>
#include <cstdint>

#define FILLV (-1000.0f)
#define NEG_BIG (-3.0e38f)

// Per-batch scratch (allocation-free rule: __device__ globals).
__device__ float g_total[512];
__device__ float g_real[512];

// ---- f32x2 / b64 helpers -------------------------------------------------
__device__ __forceinline__ unsigned long long pk2(float x, float y) {
    unsigned long long r;
    asm("mov.b64 %0, {%1, %2};" : "=l"(r) : "f"(x), "f"(y));
    return r;
}
__device__ __forceinline__ void upk2(unsigned long long a, float& x, float& y) {
    asm("mov.b64 {%0, %1}, %2;" : "=f"(x), "=f"(y) : "l"(a));
}
__device__ __forceinline__ unsigned long long fma2(unsigned long long a,
                                                   unsigned long long b,
                                                   unsigned long long c) {
    unsigned long long r;
    asm("fma.rn.f32x2 %0, %1, %2, %3;" : "=l"(r) : "l"(a), "l"(b), "l"(c));
    return r;
}
__device__ __forceinline__ unsigned long long add2(unsigned long long a,
                                                   unsigned long long b) {
    unsigned long long r;
    asm("add.rn.f32x2 %0, %1, %2;" : "=l"(r) : "l"(a), "l"(b));
    return r;
}

// ---- forward (total path score) kernel -----------------------------------
// 4 batches per CTA, grid = 128, block = 256 (R6 config — best measured).
// Thread t: column jj = t & 127, row-half h = t >> 7 (rows h*64 .. h*64+63).
// Register tables: Tc2[32] + Ep[32] (shared across all 4 batches).
// NEW: deferred scalar reduction. Per step only TWO barriers:
//   phase0 (max-plus + matvec, ILP-4) -> sync ->
//   phaseC (combine halves, contrib, publish new state using LAG-1 normalizer,
//           fire warp-reduction into double-buffered partials)        -> sync
// The cross-warp combine of step s's partials happens in phaseC of step s+1,
// off the critical path. Exactness: v = exp(phat - P) with ANY P, as long as
// contrib uses the same P — pure numerical-range choice (drift/step ~ +10).
__global__ void __launch_bounds__(256, 1)
crf_forward_kernel(const float* __restrict__ em, const float* __restrict__ trans) {
    __shared__ ulonglong2 shpv[4][64];    // per batch: {p[2m],p[2m+1] | v[2m],v[2m+1]}
    __shared__ float spc[4][256];         // per batch: per-thread partial column max
    __shared__ float spw[4][256];         // per batch: per-thread partial matvec sum
    __shared__ float scol[128];           // colmax of transitions
    __shared__ float swS[2][4][4];        // double-buffered warp partials: sum
    __shared__ float swM[2][4][4];        // double-buffered warp partials: max

    const int t  = threadIdx.x;
    const int jj = t & 127;
    const int h  = t >> 7;
    const int wi = (t >> 5) & 3;
    const int b0 = blockIdx.x * 4;
    const int rowbase = h * 64;

    // --- load T column slice, colmax, packed Tc2 / Ep tables (registers) ---
    float Tcs[64];
    float tcm = NEG_BIG;
#pragma unroll
    for (int k = 0; k < 64; ++k) {
        float tv = trans[(rowbase + k) * 128 + jj];
        Tcs[k] = tv;
        tcm = fmaxf(tcm, tv);
    }
    spc[0][t] = tcm;
    __syncthreads();
    if (t < 128) scol[t] = fmaxf(spc[0][t], spc[0][t + 128]);
    __syncthreads();
    const float colmax = scol[jj];

    unsigned long long Tc2[32], Ep[32];
#pragma unroll
    for (int k = 0; k < 32; ++k) {
        Tc2[k] = pk2(Tcs[2 * k], Tcs[2 * k + 1]);
        Ep[k]  = pk2(expf(Tcs[2 * k] - colmax), expf(Tcs[2 * k + 1] - colmax));
    }

    // --- init state for owned batches g0 = 2h, g1 = 2h+1 (normalizer P=0) ---
    {
        float p  = (jj == 126) ? 0.0f : FILLV;
        float vv = (jj == 126) ? 1.0f : 0.0f;
        int m = jj >> 1, lane = jj & 1;
        float* pvf0 = (float*)(shpv[2 * h]);
        float* pvf1 = (float*)(shpv[2 * h + 1]);
        pvf0[m * 4 + lane] = p;  pvf0[m * 4 + 2 + lane] = vv;
        pvf1[m * 4 + lane] = p;  pvf1[m * 4 + 2 + lane] = vv;
    }
    float P0 = 0.0f, P1 = 0.0f;        // normalizer used for current state's v
    float Lacc0 = 0.0f, Lacc1 = 0.0f;
    float vkeep0 = 0.0f, vkeep1 = 0.0f;
    __syncthreads();

    const float* embp0 = em + (size_t)(b0 + 2 * h) * 512 * 126;
    const float* embp1 = embp0 + 512 * 126;

    float obs_c0 = (jj < 126) ? embp0[jj] : FILLV;
    float obs_c1 = (jj < 126) ? embp1[jj] : FILLV;

    const ulonglong2* const pvA = shpv[0] + h * 32;
    const ulonglong2* const pvB = shpv[1] + h * 32;
    const ulonglong2* const pvC = shpv[2] + h * 32;
    const ulonglong2* const pvD = shpv[3] + h * 32;

    for (int s = 1; s <= 513; ++s) {
        // Prefetch next step's observations (hidden behind phase 0).
        float obs_n0, obs_n1;
        if (s + 1 <= 512) {
            obs_n0 = (jj < 126) ? embp0[(size_t)s * 126 + jj] : FILLV;
            obs_n1 = (jj < 126) ? embp1[(size_t)s * 126 + jj] : FILLV;
        } else {
            float v = (jj == 127) ? 0.0f : FILLV;  // END pseudo-row
            obs_n0 = v; obs_n1 = v;
        }

        // --- phase 0: max-plus + matvec over 64 rows x 4 batches (R6 form) ---
        float cm0A = NEG_BIG, cm1A = NEG_BIG;
        float cm0B = NEG_BIG, cm1B = NEG_BIG;
        float cm0C = NEG_BIG, cm1C = NEG_BIG;
        float cm0D = NEG_BIG, cm1D = NEG_BIG;
        unsigned long long wA = 0ULL, wB = 0ULL, wC = 0ULL, wD = 0ULL;
#pragma unroll
        for (int k = 0; k < 32; ++k) {
            ulonglong2 qA = pvA[k];
            ulonglong2 qB = pvB[k];
            ulonglong2 qC = pvC[k];
            ulonglong2 qD = pvD[k];
            float s0, s1;
            unsigned long long u;
            u = add2(qA.x, Tc2[k]); upk2(u, s0, s1);
            cm0A = fmaxf(cm0A, s0); cm1A = fmaxf(cm1A, s1);
            wA = fma2(qA.y, Ep[k], wA);
            u = add2(qB.x, Tc2[k]); upk2(u, s0, s1);
            cm0B = fmaxf(cm0B, s0); cm1B = fmaxf(cm1B, s1);
            wB = fma2(qB.y, Ep[k], wB);
            u = add2(qC.x, Tc2[k]); upk2(u, s0, s1);
            cm0C = fmaxf(cm0C, s0); cm1C = fmaxf(cm1C, s1);
            wC = fma2(qC.y, Ep[k], wC);
            u = add2(qD.x, Tc2[k]); upk2(u, s0, s1);
            cm0D = fmaxf(cm0D, s0); cm1D = fmaxf(cm1D, s1);
            wD = fma2(qD.y, Ep[k], wD);
        }
        {
            float w0, w1;
            upk2(wA, w0, w1); spc[0][t] = fmaxf(cm0A, cm1A); spw[0][t] = w0 + w1;
            upk2(wB, w0, w1); spc[1][t] = fmaxf(cm0B, cm1B); spw[1][t] = w0 + w1;
            upk2(wC, w0, w1); spc[2][t] = fmaxf(cm0C, cm1C); spw[2][t] = w0 + w1;
            upk2(wD, w0, w1); spc[3][t] = fmaxf(cm0D, cm1D); spw[3][t] = w0 + w1;
        }
        __syncthreads();

        // --- phaseC: half h handles its 2 owned batches ---
        const int g0 = 2 * h, g1 = g0 + 1;
        const int br = (s - 1) & 1, bw = s & 1;

        float c0 = fmaxf(spc[g0][jj], spc[g0][128 + jj]);
        float w0 = spw[g0][jj] + spw[g0][128 + jj];
        float contrib0 = __expf(P0 + colmax - c0) * w0;
        float pnew0 = obs_c0 + c0;
        float c1 = fmaxf(spc[g1][jj], spc[g1][128 + jj]);
        float w1 = spw[g1][jj] + spw[g1][128 + jj];
        float contrib1 = __expf(P1 + colmax - c1) * w1;
        float pnew1 = obs_c1 + c1;

        // Consume deferred partials of step s-1: Lacc += log(S_{s-1}),
        // and lag-1 normalizer = max of phat_s (exact math for any P).
        float Pn0, Pn1;
        if (s > 1) {
            float S0 = (swS[br][g0][0] + swS[br][g0][1]) + (swS[br][g0][2] + swS[br][g0][3]);
            float S1 = (swS[br][g1][0] + swS[br][g1][1]) + (swS[br][g1][2] + swS[br][g1][3]);
            Lacc0 += __logf(S0);
            Lacc1 += __logf(S1);
            Pn0 = fmaxf(fmaxf(swM[br][g0][0], swM[br][g0][1]),
                        fmaxf(swM[br][g0][2], swM[br][g0][3]));
            Pn1 = fmaxf(fmaxf(swM[br][g1][0], swM[br][g1][1]),
                        fmaxf(swM[br][g1][2], swM[br][g1][3]));
        } else {
            Pn0 = 0.0f; Pn1 = 0.0f;
        }

        // Publish new state immediately (no cross-warp wait on this path).
        float v0 = __expf(pnew0 - Pn0);
        float v1 = __expf(pnew1 - Pn1);
        vkeep0 = v0; vkeep1 = v1;
        {
            int m = jj >> 1, lane = jj & 1;
            float* pvf0 = (float*)(shpv[g0]);
            float* pvf1 = (float*)(shpv[g1]);
            pvf0[m * 4 + lane] = pnew0;  pvf0[m * 4 + 2 + lane] = v0;
            pvf1[m * 4 + lane] = pnew1;  pvf1[m * 4 + 2 + lane] = v1;
        }

        // Fire this step's warp reduction into buffer bw (read next step).
        float sr0 = contrib0, mr0 = pnew0;
        float sr1 = contrib1, mr1 = pnew1;
#pragma unroll
        for (int o = 16; o; o >>= 1) {
            float a0 = __shfl_xor_sync(0xffffffffu, sr0, o);
            float m0 = __shfl_xor_sync(0xffffffffu, mr0, o);
            float a1 = __shfl_xor_sync(0xffffffffu, sr1, o);
            float m1 = __shfl_xor_sync(0xffffffffu, mr1, o);
            sr0 += a0; mr0 = fmaxf(mr0, m0);
            sr1 += a1; mr1 = fmaxf(mr1, m1);
        }
        if ((t & 31) == 0) {
            swS[bw][g0][wi] = sr0; swM[bw][g0][wi] = mr0;
            swS[bw][g1][wi] = sr1; swM[bw][g1][wi] = mr1;
        }

        P0 = Pn0; P1 = Pn1;
        __syncthreads();
        obs_c0 = obs_n0;
        obs_c1 = obs_n1;
    }

    // --- epilogue: flush step-513 partials, final log-sum-exp ---
    const int g0 = 2 * h, g1 = g0 + 1;
    {
        // step 513 wrote buffer 1
        float S0 = (swS[1][g0][0] + swS[1][g0][1]) + (swS[1][g0][2] + swS[1][g0][3]);
        float S1 = (swS[1][g1][0] + swS[1][g1][1]) + (swS[1][g1][2] + swS[1][g1][3]);
        Lacc0 += __logf(S0);
        Lacc1 += __logf(S1);
    }
    {
        float sr0 = vkeep0, sr1 = vkeep1;
#pragma unroll
        for (int o = 16; o; o >>= 1) {
            sr0 += __shfl_xor_sync(0xffffffffu, sr0, o);
            sr1 += __shfl_xor_sync(0xffffffffu, sr1, o);
        }
        if ((t & 31) == 0) {
            swS[0][g0][wi] = sr0;
            swS[0][g1][wi] = sr1;
        }
    }
    __syncthreads();
    if (jj == 0) {
        float Sf0 = (swS[0][g0][0] + swS[0][g0][1]) + (swS[0][g0][2] + swS[0][g0][3]);
        float Sf1 = (swS[0][g1][0] + swS[0][g1][1]) + (swS[0][g1][2] + swS[0][g1][3]);
        // P0/P1 = normalizer used for the final published v (exact identity)
        g_total[b0 + g0] = P0 + logf(Sf0) + Lacc0;
        g_total[b0 + g1] = P1 + logf(Sf1) + Lacc1;
    }
}

// ---- gold-path score kernel ----------------------------------------------
__global__ void crf_real_kernel(const float* __restrict__ em,
                                const int* __restrict__ labels,
                                const float* __restrict__ trans) {
    const int b = blockIdx.x;
    const int t = threadIdx.x;   // 128 threads
    __shared__ float sw[4];
    const int* lb = labels + b * 512;
    const float* emb = em + (size_t)b * 512 * 126;

    float acc = 0.0f;
    for (int tt = t; tt < 512; tt += 128) {
        int l0 = lb[tt];
        acc += emb[tt * 126 + l0];
        int l1 = (tt < 511) ? lb[tt + 1] : 127;     // END = L+1 = 127
        acc += trans[l0 * 128 + l1];
    }
    if (t == 0) acc += trans[126 * 128 + lb[0]];     // START = L = 126

#pragma unroll
    for (int o = 16; o; o >>= 1) acc += __shfl_xor_sync(0xffffffffu, acc, o);
    if ((t & 31) == 0) sw[t >> 5] = acc;
    __syncthreads();
    if (t == 0) g_real[b] = (sw[0] + sw[1]) + (sw[2] + sw[3]);
}

// ---- fixed-order final reduction (deterministic) -------------------------
__global__ void crf_reduce_kernel(float* __restrict__ out) {
    const int t = threadIdx.x;   // 512 threads
    __shared__ float sw[16];
    float d = g_total[t] - g_real[t];
#pragma unroll
    for (int o = 16; o; o >>= 1) d += __shfl_xor_sync(0xffffffffu, d, o);
    if ((t & 31) == 0) sw[t >> 5] = d;
    __syncthreads();
    if (t == 0) {
        float s = 0.0f;
#pragma unroll
        for (int w = 0; w < 16; ++w) s += sw[w];
        out[0] = s;
    }
}

extern "C" void kernel_launch(void* const* d_in, const int* in_sizes, int n_in,
                              void* d_out, int out_size) {
    const float* em     = (const float*)d_in[0];   // [512, 512, 126] f32
    const int*   labels = (const int*)d_in[1];     // [512, 512] i32
    const float* trans  = (const float*)d_in[2];   // [128, 128] f32

    crf_forward_kernel<<<128, 256>>>(em, trans);
    crf_real_kernel<<<512, 128>>>(em, labels, trans);
    crf_reduce_kernel<<<1, 512>>>((float*)d_out);
}

// round 12
// speedup vs baseline: 1.4493x; 1.0098x over previous
#include <cuda_runtime.h>
#include <cstdint>

#define FILLV (-1000.0f)
#define NEG_BIG (-3.0e38f)

// Per-batch scratch (allocation-free rule: __device__ globals).
__device__ float g_total[512];
__device__ float g_real[512];

// ---- f32x2 / b64 helpers -------------------------------------------------
__device__ __forceinline__ unsigned long long pk2(float x, float y) {
    unsigned long long r;
    asm("mov.b64 %0, {%1, %2};" : "=l"(r) : "f"(x), "f"(y));
    return r;
}
__device__ __forceinline__ void upk2(unsigned long long a, float& x, float& y) {
    asm("mov.b64 {%0, %1}, %2;" : "=f"(x), "=f"(y) : "l"(a));
}
__device__ __forceinline__ unsigned long long fma2(unsigned long long a,
                                                   unsigned long long b,
                                                   unsigned long long c) {
    unsigned long long r;
    asm("fma.rn.f32x2 %0, %1, %2, %3;" : "=l"(r) : "l"(a), "l"(b), "l"(c));
    return r;
}
__device__ __forceinline__ unsigned long long add2(unsigned long long a,
                                                   unsigned long long b) {
    unsigned long long r;
    asm("add.rn.f32x2 %0, %1, %2;" : "=l"(r) : "l"(a), "l"(b));
    return r;
}

// ---- forward (total path score) kernel -----------------------------------
// 4 batches per CTA, grid = 128, block = 256 (proven best config).
// Thread t: column jj = t & 127, row-half h = t >> 7 (rows h*64 .. h*64+63).
// Register tables: Tc2[32] + Ep[32] (shared across all 4 batches).
// FULLY deferred scalar work. Per step:
//   [deferred section for step s-1: contrib exp, 4-chain shfl reduction,
//    swS/swM stores — interleaved with phase 0, OFF the critical path]
//   phase0 (max-plus + matvec, ILP-4) -> BAR ->
//   phaseC (c,w combine; pnew = obs + c; v = exp(pnew − M_{s-1}); publish pv;
//           Lacc += log S_{s-1})                                      -> BAR
// Exactness: v = exp(phat − P) for ANY P used consistently; contrib for step s
// uses P = M_{s-2} (normalizer in effect when w_s's v was published).
__global__ void __launch_bounds__(256, 1)
crf_forward_kernel(const float* __restrict__ em, const float* __restrict__ trans) {
    __shared__ ulonglong2 shpv[4][64];    // per batch: {p[2m],p[2m+1] | v[2m],v[2m+1]}
    __shared__ float2 spcw[4][256];       // per batch: per-thread (colmax partial, matvec partial)
    __shared__ float scol[128];           // colmax of transitions
    __shared__ float swS[4][4];           // warp partials: sum(contrib)
    __shared__ float swM[4][4];           // warp partials: max(pnew)

    const int t  = threadIdx.x;
    const int jj = t & 127;
    const int h  = t >> 7;
    const int wi = (t >> 5) & 3;
    const int b0 = blockIdx.x * 4;
    const int rowbase = h * 64;
    const int g0 = 2 * h, g1 = g0 + 1;

    // --- load T column slice, colmax, packed Tc2 / Ep tables (registers) ---
    float Tcs[64];
    float tcm = NEG_BIG;
#pragma unroll
    for (int k = 0; k < 64; ++k) {
        float tv = trans[(rowbase + k) * 128 + jj];
        Tcs[k] = tv;
        tcm = fmaxf(tcm, tv);
    }
    spcw[0][t].x = tcm;
    __syncthreads();
    if (t < 128) scol[t] = fmaxf(spcw[0][t].x, spcw[0][t + 128].x);
    __syncthreads();
    const float colmax = scol[jj];

    unsigned long long Tc2[32], Ep[32];
#pragma unroll
    for (int k = 0; k < 32; ++k) {
        Tc2[k] = pk2(Tcs[2 * k], Tcs[2 * k + 1]);
        Ep[k]  = pk2(expf(Tcs[2 * k] - colmax), expf(Tcs[2 * k + 1] - colmax));
    }

    // --- init state for owned batches (normalizer P = 0) ---
    {
        float p  = (jj == 126) ? 0.0f : FILLV;
        float vv = (jj == 126) ? 1.0f : 0.0f;
        int m = jj >> 1, lane = jj & 1;
        float* pvf0 = (float*)(shpv[g0]);
        float* pvf1 = (float*)(shpv[g1]);
        pvf0[m * 4 + lane] = p;  pvf0[m * 4 + 2 + lane] = vv;
        pvf1[m * 4 + lane] = p;  pvf1[m * 4 + 2 + lane] = vv;
    }
    float P0 = 0.0f, P1 = 0.0f;         // normalizer of currently-published v
    float PdP0 = 0.0f, PdP1 = 0.0f;     // normalizer of w at prev step (lag-2)
    float cP0 = 0.0f, cP1 = 0.0f;       // prev step c (deferred contrib input)
    float wP0 = 0.0f, wP1 = 0.0f;       // prev step w
    float pnP0 = 0.0f, pnP1 = 0.0f;     // prev step pnew (deferred max input)
    float Lacc0 = 0.0f, Lacc1 = 0.0f;
    float vkeep0 = 0.0f, vkeep1 = 0.0f;
    __syncthreads();

    const float* embp0 = em + (size_t)(b0 + g0) * 512 * 126;
    const float* embp1 = embp0 + 512 * 126;

    float obs_c0 = (jj < 126) ? embp0[jj] : FILLV;
    float obs_c1 = (jj < 126) ? embp1[jj] : FILLV;

    const ulonglong2* const pvA = shpv[0] + h * 32;
    const ulonglong2* const pvB = shpv[1] + h * 32;
    const ulonglong2* const pvC = shpv[2] + h * 32;
    const ulonglong2* const pvD = shpv[3] + h * 32;

    for (int s = 1; s <= 513; ++s) {
        // --- deferred section for step s-1 (interleaves with phase 0) ---
        if (s > 1) {
            float contrib0 = __expf(PdP0 + colmax - cP0) * wP0;
            float contrib1 = __expf(PdP1 + colmax - cP1) * wP1;
            float sr0 = contrib0, mr0 = pnP0;
            float sr1 = contrib1, mr1 = pnP1;
#pragma unroll
            for (int o = 16; o; o >>= 1) {
                float a0 = __shfl_xor_sync(0xffffffffu, sr0, o);
                float m0 = __shfl_xor_sync(0xffffffffu, mr0, o);
                float a1 = __shfl_xor_sync(0xffffffffu, sr1, o);
                float m1 = __shfl_xor_sync(0xffffffffu, mr1, o);
                sr0 += a0; mr0 = fmaxf(mr0, m0);
                sr1 += a1; mr1 = fmaxf(mr1, m1);
            }
            if ((t & 31) == 0) {
                swS[g0][wi] = sr0; swM[g0][wi] = mr0;
                swS[g1][wi] = sr1; swM[g1][wi] = mr1;
            }
        }

        // Prefetch next step's observations (hidden behind phase 0).
        float obs_n0, obs_n1;
        if (s + 1 <= 512) {
            obs_n0 = (jj < 126) ? embp0[(size_t)s * 126 + jj] : FILLV;
            obs_n1 = (jj < 126) ? embp1[(size_t)s * 126 + jj] : FILLV;
        } else {
            float v = (jj == 127) ? 0.0f : FILLV;  // END pseudo-row
            obs_n0 = v; obs_n1 = v;
        }

        // --- phase 0: max-plus + matvec over 64 rows x 4 batches ---
        float cm0A = NEG_BIG, cm1A = NEG_BIG;
        float cm0B = NEG_BIG, cm1B = NEG_BIG;
        float cm0C = NEG_BIG, cm1C = NEG_BIG;
        float cm0D = NEG_BIG, cm1D = NEG_BIG;
        unsigned long long wA = 0ULL, wB = 0ULL, wC = 0ULL, wD = 0ULL;
#pragma unroll
        for (int k = 0; k < 32; ++k) {
            ulonglong2 qA = pvA[k];
            ulonglong2 qB = pvB[k];
            ulonglong2 qC = pvC[k];
            ulonglong2 qD = pvD[k];
            float s0, s1;
            unsigned long long u;
            u = add2(qA.x, Tc2[k]); upk2(u, s0, s1);
            cm0A = fmaxf(cm0A, s0); cm1A = fmaxf(cm1A, s1);
            wA = fma2(qA.y, Ep[k], wA);
            u = add2(qB.x, Tc2[k]); upk2(u, s0, s1);
            cm0B = fmaxf(cm0B, s0); cm1B = fmaxf(cm1B, s1);
            wB = fma2(qB.y, Ep[k], wB);
            u = add2(qC.x, Tc2[k]); upk2(u, s0, s1);
            cm0C = fmaxf(cm0C, s0); cm1C = fmaxf(cm1C, s1);
            wC = fma2(qC.y, Ep[k], wC);
            u = add2(qD.x, Tc2[k]); upk2(u, s0, s1);
            cm0D = fmaxf(cm0D, s0); cm1D = fmaxf(cm1D, s1);
            wD = fma2(qD.y, Ep[k], wD);
        }
        {
            float w0, w1;
            upk2(wA, w0, w1); spcw[0][t] = make_float2(fmaxf(cm0A, cm1A), w0 + w1);
            upk2(wB, w0, w1); spcw[1][t] = make_float2(fmaxf(cm0B, cm1B), w0 + w1);
            upk2(wC, w0, w1); spcw[2][t] = make_float2(fmaxf(cm0C, cm1C), w0 + w1);
            upk2(wD, w0, w1); spcw[3][t] = make_float2(fmaxf(cm0D, cm1D), w0 + w1);
        }
        __syncthreads();

        // --- phaseC: minimal critical path for owned batches ---
        float2 x0 = spcw[g0][jj], y0 = spcw[g0][128 + jj];
        float2 x1 = spcw[g1][jj], y1 = spcw[g1][128 + jj];
        float c0 = fmaxf(x0.x, y0.x), w0 = x0.y + y0.y;
        float c1 = fmaxf(x1.x, y1.x), w1 = x1.y + y1.y;
        float pnew0 = obs_c0 + c0;
        float pnew1 = obs_c1 + c1;

        float M0, M1;
        if (s > 1) {
            M0 = fmaxf(fmaxf(swM[g0][0], swM[g0][1]), fmaxf(swM[g0][2], swM[g0][3]));
            M1 = fmaxf(fmaxf(swM[g1][0], swM[g1][1]), fmaxf(swM[g1][2], swM[g1][3]));
        } else {
            M0 = 0.0f; M1 = 0.0f;
        }

        float v0 = __expf(pnew0 - M0);
        float v1 = __expf(pnew1 - M1);
        vkeep0 = v0; vkeep1 = v1;
        {
            int m = jj >> 1, lane = jj & 1;
            float* pvf0 = (float*)(shpv[g0]);
            float* pvf1 = (float*)(shpv[g1]);
            pvf0[m * 4 + lane] = pnew0;  pvf0[m * 4 + 2 + lane] = v0;
            pvf1[m * 4 + lane] = pnew1;  pvf1[m * 4 + 2 + lane] = v1;
        }

        // Off-path accumulation: Lacc += log(S_{s-1})
        if (s > 1) {
            float S0 = (swS[g0][0] + swS[g0][1]) + (swS[g0][2] + swS[g0][3]);
            float S1 = (swS[g1][0] + swS[g1][1]) + (swS[g1][2] + swS[g1][3]);
            Lacc0 += __logf(S0);
            Lacc1 += __logf(S1);
        }

        // Roll deferred state: normalizer of w_{s+1}'s v is M_{s-1} (new P);
        // contrib_s (deferred to s+1) needs the OLD P (= M_{s-2}).
        PdP0 = P0; PdP1 = P1;
        P0 = M0;  P1 = M1;
        cP0 = c0; cP1 = c1;
        wP0 = w0; wP1 = w1;
        pnP0 = pnew0; pnP1 = pnew1;

        __syncthreads();
        obs_c0 = obs_n0;
        obs_c1 = obs_n1;
    }

    // --- epilogue: flush step-513 deferred contrib + final log-sum-exp ---
    {
        float contrib0 = __expf(PdP0 + colmax - cP0) * wP0;
        float contrib1 = __expf(PdP1 + colmax - cP1) * wP1;
        float sr0 = contrib0, sv0 = vkeep0;
        float sr1 = contrib1, sv1 = vkeep1;
#pragma unroll
        for (int o = 16; o; o >>= 1) {
            sr0 += __shfl_xor_sync(0xffffffffu, sr0, o);
            sv0 += __shfl_xor_sync(0xffffffffu, sv0, o);
            sr1 += __shfl_xor_sync(0xffffffffu, sr1, o);
            sv1 += __shfl_xor_sync(0xffffffffu, sv1, o);
        }
        if ((t & 31) == 0) {
            swS[g0][wi] = sr0; swM[g0][wi] = sv0;   // swM reused as sum(v)
            swS[g1][wi] = sr1; swM[g1][wi] = sv1;
        }
    }
    __syncthreads();
    if (jj == 0) {
        float S0 = (swS[g0][0] + swS[g0][1]) + (swS[g0][2] + swS[g0][3]);
        float S1 = (swS[g1][0] + swS[g1][1]) + (swS[g1][2] + swS[g1][3]);
        float Sv0 = (swM[g0][0] + swM[g0][1]) + (swM[g0][2] + swM[g0][3]);
        float Sv1 = (swM[g1][0] + swM[g1][1]) + (swM[g1][2] + swM[g1][3]);
        // P0/P1 = normalizer of the final published v (exact identity)
        g_total[b0 + g0] = P0 + logf(Sv0) + Lacc0 + logf(S0);
        g_total[b0 + g1] = P1 + logf(Sv1) + Lacc1 + logf(S1);
    }
}

// ---- gold-path score kernel ----------------------------------------------
__global__ void crf_real_kernel(const float* __restrict__ em,
                                const int* __restrict__ labels,
                                const float* __restrict__ trans) {
    const int b = blockIdx.x;
    const int t = threadIdx.x;   // 128 threads
    __shared__ float sw[4];
    const int* lb = labels + b * 512;
    const float* emb = em + (size_t)b * 512 * 126;

    float acc = 0.0f;
    for (int tt = t; tt < 512; tt += 128) {
        int l0 = lb[tt];
        acc += emb[tt * 126 + l0];
        int l1 = (tt < 511) ? lb[tt + 1] : 127;     // END = L+1 = 127
        acc += trans[l0 * 128 + l1];
    }
    if (t == 0) acc += trans[126 * 128 + lb[0]];     // START = L = 126

#pragma unroll
    for (int o = 16; o; o >>= 1) acc += __shfl_xor_sync(0xffffffffu, acc, o);
    if ((t & 31) == 0) sw[t >> 5] = acc;
    __syncthreads();
    if (t == 0) g_real[b] = (sw[0] + sw[1]) + (sw[2] + sw[3]);
}

// ---- fixed-order final reduction (deterministic) -------------------------
__global__ void crf_reduce_kernel(float* __restrict__ out) {
    const int t = threadIdx.x;   // 512 threads
    __shared__ float sw[16];
    float d = g_total[t] - g_real[t];
#pragma unroll
    for (int o = 16; o; o >>= 1) d += __shfl_xor_sync(0xffffffffu, d, o);
    if ((t & 31) == 0) sw[t >> 5] = d;
    __syncthreads();
    if (t == 0) {
        float s = 0.0f;
#pragma unroll
        for (int w = 0; w < 16; ++w) s += sw[w];
        out[0] = s;
    }
}

extern "C" void kernel_launch(void* const* d_in, const int* in_sizes, int n_in,
                              void* d_out, int out_size) {
    const float* em     = (const float*)d_in[0];   // [512, 512, 126] f32
    const int*   labels = (const int*)d_in[1];     // [512, 512] i32
    const float* trans  = (const float*)d_in[2];   // [128, 128] f32

    crf_forward_kernel<<<128, 256>>>(em, trans);
    crf_real_kernel<<<512, 128>>>(em, labels, trans);
    crf_reduce_kernel<<<1, 512>>>((float*)d_out);
}